// round 12
// baseline (speedup 1.0000x reference)
#include <cuda_runtime.h>
#include <cuda_bf16.h>
#include <cstddef>

// Problem constants
#define BB   1024   // batch
#define TT   336    // time steps
#define II   16     // input features
#define HH   64     // hidden
#define GG   256    // 4*H gates

// LSTM batch partition over all 148 SMs: 136 blocks x 7 rows + 12 blocks x 6 rows
#define LBLK  148
#define RMAX  7
#define NB7   136   // blocks with 7 rows; rest have 6

// Scratch (device globals: allocation inside kernel_launch is forbidden)
__device__ float g_xp[(size_t)TT * BB * GG];   // [T][B][4H] layer-1 input-projection pre-activations
__device__ float g_h1[(size_t)TT * BB * HH];   // [T][B][H] layer-0 hidden outputs
__device__ float g_h2[(size_t)BB * HH];        // [B][H] layer-1 last hidden

__device__ __forceinline__ float sigf(float x) { return 1.0f / (1.0f + __expf(-x)); }
// fast tanh: clamp (avoids inf/inf NaN), then (e^2x-1)/(e^2x+1). abs err ~1e-7.
__device__ __forceinline__ float tanh_fast(float x) {
    x = fminf(fmaxf(x, -15.0f), 15.0f);
    float E = __expf(2.0f * x);
    return __fdividef(E - 1.0f, E + 1.0f);
}

// ---- packed f32x2 helpers (FFMA2: 2 lane-FMAs per issue slot; PTX-only path) ----
typedef unsigned long long u64;

__device__ __forceinline__ u64 pack2(float lo, float hi) {
    u64 r; asm("mov.b64 %0, {%1, %2};" : "=l"(r) : "f"(lo), "f"(hi)); return r;
}
__device__ __forceinline__ void unpack2(u64 v, float& lo, float& hi) {
    asm("mov.b64 {%0, %1}, %2;" : "=f"(lo), "=f"(hi) : "l"(v));
}
__device__ __forceinline__ u64 fma2(u64 a, u64 b, u64 c) {
    u64 d; asm("fma.rn.f32x2 %0, %1, %2, %3;" : "=l"(d) : "l"(a), "l"(b), "l"(c)); return d;
}
__device__ __forceinline__ float hsum2(u64 a) {
    float lo, hi; unpack2(a, lo, hi); return lo + hi;
}

// ---------------------------------------------------------------------------
// Fused LSTM recurrence, 1024 threads, 4-way split-K, 148 blocks (7 rows each,
// last 12 have 6).
// LAYER==0: gates = x[t]·Wih0 + h·Whh0 + bias (input proj fused; proj0 kernel
//           eliminated). x[t+1] staged into shared 1 step ahead by 28 loader
//           threads (tid 448..475, idle in phase 2).
// LAYER==1: gates = xp[t] (from g_xp, biases included) + h·Whh1. xp[t+1]
//           staged by 448 loader threads (tid 448..895).
// Phase 1: thread (g = tid&255, q = tid>>8) computes the K-quarter partial of
//          gate g across RMAX rows (weights in regs as f32x2 pairs, h broadcast
//          via LDS.128). Partials -> gP[q].
// Phase 2: thread tid<448 owns one (row, unit): sums 4 partials, activations
//          (fast tanh), c in a register, h_s (+ g_h1 / g_h2).
// Two barriers/step: H1 gates(write->read), H2 h(write->next-step read).
// Staging-buffer ordering: write (t+1)&1 pre-H1(t); read post-H2(t) — safe.
// ---------------------------------------------------------------------------
template <int LAYER>
__global__ void __launch_bounds__(1024, 1) lstm_fused(const float* __restrict__ x,
                                                      const float* __restrict__ Wih,
                                                      const float* __restrict__ Whh,
                                                      const float* __restrict__ bih,
                                                      const float* __restrict__ bhh) {
    __shared__ __align__(16) float h_s[RMAX * HH];        // 1.75KB
    __shared__ __align__(16) float gP[4][RMAX * GG];      // 28KB
    __shared__ __align__(16) float xstage[2][RMAX][GG];   // 14KB (L0 uses cols 0..15)

    const int tid = threadIdx.x;
    const int g = tid & 255;
    const int q = tid >> 8;           // K-quarter 0..3
    const int bid = blockIdx.x;
    const int rows = (bid < NB7) ? 7 : 6;
    const int b0 = (bid < NB7) ? bid * 7 : NB7 * 7 + (bid - NB7) * 6;

    // Whh K-quarter: 16 floats -> 8 f32x2 pairs in registers
    u64 w2[8];
    {
        const ulonglong2* Wv = reinterpret_cast<const ulonglong2*>(Whh + (size_t)g * HH + q * 16);
        #pragma unroll
        for (int k = 0; k < 4; ++k) { ulonglong2 v = Wv[k]; w2[2*k] = v.x; w2[2*k+1] = v.y; }
    }
    // Layer-0 extras: Wih K-quarter (4 floats -> 2 pairs) + bias sum
    u64 wi0 = 0, wi1 = 0; float bsum = 0.0f;
    if (LAYER == 0) {
        ulonglong2 v = *reinterpret_cast<const ulonglong2*>(Wih + (size_t)g * II + q * 4);
        wi0 = v.x; wi1 = v.y;
        bsum = bih[g] + bhh[g];
    }

    for (int idx = tid; idx < RMAX * HH; idx += 1024) h_s[idx] = 0.0f;

    // loader role (disjoint from phase-2 threads tid<448)
    const int nload = (LAYER == 0) ? 28 : 448;
    const bool loader = (tid >= 448) && (tid < 448 + nload);
    const float* lsrc = nullptr; size_t lstep = 0;
    float* ldst0 = nullptr; float* ldst1 = nullptr;
    if (loader) {
        const int j = tid - 448;
        const int row  = (LAYER == 0) ? (j >> 2) : (j >> 6);
        const int col4 = (LAYER == 0) ? ((j & 3) << 2) : ((j & 63) << 2);
        int brow = b0 + row; if (brow > BB - 1) brow = BB - 1;   // phantom clamp
        if (LAYER == 0) { lsrc = x + ((size_t)brow * TT) * II + col4; lstep = II; }
        else            { lsrc = g_xp + (size_t)brow * GG + col4; lstep = (size_t)BB * GG; }
        ldst0 = &xstage[0][row][col4];
        ldst1 = &xstage[1][row][col4];
        // preload t=0 into buffer 0
        *reinterpret_cast<float4*>(ldst0) = *reinterpret_cast<const float4*>(lsrc);
    }

    // phase-2 role: one (row, unit) per thread
    const int r2 = tid >> 6;
    const int u2 = tid & 63;
    const bool p2 = (tid < RMAX * 64) && (r2 < rows);
    const int r2c = p2 ? r2 : 0;
    float* const p2h  = h_s + r2c * HH + u2;
    float* const p2g1 = g_h1 + (size_t)(b0 + r2c) * HH + u2;   // + t*BB*HH per step
    float* const p2g2 = g_h2 + (size_t)(b0 + r2c) * HH + u2;
    float c = 0.0f;

    __syncthreads();

    #pragma unroll 1
    for (int t = 0; t < TT; ++t) {
        // prefetch next step's x / xp (latency covered by this step's phase 1)
        float4 lv;
        const bool doload = loader && (t + 1 < TT);
        if (doload) lv = *reinterpret_cast<const float4*>(lsrc + (size_t)(t + 1) * lstep);

        const float* const xrow = &xstage[t & 1][0][0];

        u64 acc[RMAX];
        if (q == 0) {
            if (LAYER == 0) {
                #pragma unroll
                for (int b = 0; b < RMAX; ++b) acc[b] = pack2(bsum, 0.0f);
            } else {
                #pragma unroll
                for (int b = 0; b < RMAX; ++b) acc[b] = pack2(xrow[b * GG + g], 0.0f);
            }
        } else {
            #pragma unroll
            for (int b = 0; b < RMAX; ++b) acc[b] = pack2(0.0f, 0.0f);
        }

        if (LAYER == 0) {
            // fused input projection: + x[b][t][q*4..q*4+3] · Wih[g][q*4..q*4+3]
            #pragma unroll
            for (int b = 0; b < RMAX; ++b) {
                ulonglong2 xv = *reinterpret_cast<const ulonglong2*>(xrow + b * GG + q * 4);
                acc[b] = fma2(xv.x, wi0, acc[b]);
                acc[b] = fma2(xv.y, wi1, acc[b]);
            }
        }

        // recurrent K-quarter: acc[b] += sum_j h[b][q*16+j] * Whh[g][q*16+j]
        const float* const hb = h_s + q * 16;
        #pragma unroll
        for (int k = 0; k < 4; ++k) {
            const u64 wA = w2[2*k], wB = w2[2*k+1];
            #pragma unroll
            for (int b = 0; b < RMAX; ++b) {
                ulonglong2 h2 = *reinterpret_cast<const ulonglong2*>(hb + b * HH + k * 4);
                acc[b] = fma2(h2.x, wA, acc[b]);
                acc[b] = fma2(h2.y, wB, acc[b]);
            }
        }
        {
            float* gp = gP[q] + g;
            #pragma unroll
            for (int b = 0; b < RMAX; ++b) gp[b * GG] = hsum2(acc[b]);
        }
        // stage prefetched data into the other buffer ((t+1)&1)
        if (doload) *((t & 1) ? reinterpret_cast<float4*>(ldst0)
                              : reinterpret_cast<float4*>(ldst1)) = lv;
        __syncthreads();   // H1: gate partials (and staged x) visible

        if (p2) {
            const float* a0 = gP[0] + r2 * GG + u2;
            const float* a1 = gP[1] + r2 * GG + u2;
            const float* a2 = gP[2] + r2 * GG + u2;
            const float* a3 = gP[3] + r2 * GG + u2;
            float s0 = (a0[0]   + a1[0])   + (a2[0]   + a3[0]);
            float s1 = (a0[64]  + a1[64])  + (a2[64]  + a3[64]);
            float s2 = (a0[128] + a1[128]) + (a2[128] + a3[128]);
            float s3 = (a0[192] + a1[192]) + (a2[192] + a3[192]);
            float iv = sigf(s0);
            float fv = sigf(s1);
            float gv = tanh_fast(s2);
            float ov = sigf(s3);
            float cn = fmaf(fv, c, iv * gv);
            c = cn;
            float hn = ov * tanh_fast(cn);
            *p2h = hn;
            if (LAYER == 0) p2g1[(size_t)t * BB * HH] = hn;
            else if (t == TT - 1) *p2g2 = hn;
        }
        __syncthreads();   // H2: h updated before next step's phase 1
    }
}

// ---------------------------------------------------------------------------
// proj1: g_xp[t][b][g] = sum_j g_h1[t][b][j] * Wih1[g][j] + bih1[g] + bhh1[g]
// 64 (t,b) pairs per block, 256 threads = one thread per gate g. K=64.
// ---------------------------------------------------------------------------
#define P1P 64
__global__ void __launch_bounds__(256) proj1_kernel(const float* __restrict__ Wih,
                                                    const float* __restrict__ bih,
                                                    const float* __restrict__ bhh) {
    __shared__ __align__(16) float hs[P1P * HH];   // 16KB
    const int tid = threadIdx.x;
    const int g = tid;
    const float bsum = bih[g] + bhh[g];

    const int n0 = blockIdx.x * P1P;
    {
        const float4* src = reinterpret_cast<const float4*>(g_h1 + (size_t)n0 * HH);
        float4* dst = reinterpret_cast<float4*>(hs);
        #pragma unroll 4
        for (int idx = tid; idx < (P1P * HH) / 4; idx += 256) dst[idx] = src[idx];
    }
    u64 w2[32];
    {
        const ulonglong2* Wv = reinterpret_cast<const ulonglong2*>(Wih + (size_t)g * HH);
        #pragma unroll
        for (int k = 0; k < 16; ++k) { ulonglong2 v = Wv[k]; w2[2*k] = v.x; w2[2*k+1] = v.y; }
    }
    __syncthreads();

    #pragma unroll 2
    for (int p = 0; p < P1P; ++p) {
        const ulonglong2* hv = reinterpret_cast<const ulonglong2*>(hs + p * HH);
        u64 accA = pack2(bsum, 0.0f), accB = pack2(0.0f, 0.0f);
        #pragma unroll
        for (int k = 0; k < 16; ++k) {
            ulonglong2 h2 = hv[k];
            accA = fma2(h2.x, w2[2*k],   accA);
            accB = fma2(h2.y, w2[2*k+1], accB);
        }
        g_xp[(size_t)(n0 + p) * GG + g] = hsum2(accA) + hsum2(accB);
    }
}

// ---------------------------------------------------------------------------
// FC: out[b] = dot(g_h2[b], Wfc) + bfc
// ---------------------------------------------------------------------------
__global__ void __launch_bounds__(128) fc_kernel(const float* __restrict__ Wfc,
                                                 const float* __restrict__ bfc,
                                                 float* __restrict__ out) {
    __shared__ float w_s[HH];
    const int tid = threadIdx.x;
    if (tid < HH) w_s[tid] = Wfc[tid];
    __syncthreads();
    const int b = blockIdx.x * 128 + tid;
    if (b < BB) {
        const float* hp = g_h2 + (size_t)b * HH;
        float a = bfc[0];
        #pragma unroll
        for (int j = 0; j < HH; ++j) a = fmaf(hp[j], w_s[j], a);
        out[b] = a;
    }
}

extern "C" void kernel_launch(void* const* d_in, const int* in_sizes, int n_in,
                              void* d_out, int out_size) {
    const float* x    = (const float*)d_in[0];
    const float* Wih0 = (const float*)d_in[1];
    const float* Whh0 = (const float*)d_in[2];
    const float* bih0 = (const float*)d_in[3];
    const float* bhh0 = (const float*)d_in[4];
    const float* Wih1 = (const float*)d_in[5];
    const float* Whh1 = (const float*)d_in[6];
    const float* bih1 = (const float*)d_in[7];
    const float* bhh1 = (const float*)d_in[8];
    const float* Wfc  = (const float*)d_in[9];
    const float* bfc  = (const float*)d_in[10];
    float* out = (float*)d_out;

    // layer 0: fused input projection + recurrence (proj0 kernel eliminated)
    lstm_fused<0><<<LBLK, 1024>>>(x, Wih0, Whh0, bih0, bhh0);
    // layer 1 input projection (K=64) from g_h1
    proj1_kernel<<<(TT * BB) / P1P, 256>>>(Wih1, bih1, bhh1);
    // layer 1: recurrence reading staged g_xp
    lstm_fused<1><<<LBLK, 1024>>>(nullptr, nullptr, Whh1, nullptr, nullptr);
    // final FC
    fc_kernel<<<(BB + 127) / 128, 128>>>(Wfc, bfc, out);
}